// round 2
// baseline (speedup 1.0000x reference)
#include <cuda_runtime.h>
#include <math.h>

#define B_ 4
#define S_ 4096
#define D_ 4096
#define H_ 128
#define E_ 8
#define M_ (B_*S_)

#define MT 128      // M tile per CTA
#define KC 32       // K chunk
#define XPAD 132    // padded row length for transposed X tile (16B-aligned rows, reduced bank conflicts)
#define NTHREADS 256

// -------- device globals (scratch; no allocation allowed) --------
__device__ float g_hpart[B_][32][H_];
__device__ float g_task_w[B_][E_];
__device__ float g_alpha;

// ---------------- packed f32x2 helpers ----------------
__device__ __forceinline__ unsigned long long pack_dup(float x) {
    unsigned long long r;
    unsigned u = __float_as_uint(x);
    asm("mov.b64 %0, {%1, %1};" : "=l"(r) : "r"(u));
    return r;
}
__device__ __forceinline__ void fma2(unsigned long long& c, unsigned long long a, unsigned long long b) {
    asm("fma.rn.f32x2 %0, %1, %2, %0;" : "+l"(c) : "l"(a), "l"(b));
}
__device__ __forceinline__ float2 unpack2(unsigned long long c) {
    unsigned lo, hi;
    asm("mov.b64 {%0, %1}, %2;" : "=r"(lo), "=r"(hi) : "l"(c));
    return make_float2(__uint_as_float(lo), __uint_as_float(hi));
}

// ---------------- task router: partial h ----------------
// grid (32, B_), 128 threads. block (c,b): h-partials over d in [c*128, c*128+128)
__global__ void task_partial_kernel(const float* __restrict__ task,
                                    const float* __restrict__ TW1) {
    int c = blockIdx.x, b = blockIdx.y, t = threadIdx.x;
    const float* tp = task + (size_t)b * D_ + c * 128;
    const float* w  = TW1 + (size_t)(c * 128) * H_ + t;
    float acc = 0.f;
#pragma unroll 8
    for (int d = 0; d < 128; d++)
        acc += tp[d] * w[(size_t)d * H_];
    g_hpart[b][c][t] = acc;
}

// ---------------- task router: finish ----------------
// 1 block, 128 threads
__global__ void task_finish_kernel(const float* __restrict__ Tb1,
                                   const float* __restrict__ TW2,
                                   const float* __restrict__ Tb2,
                                   const float* __restrict__ alpha) {
    __shared__ float hsm[B_][H_];
    __shared__ float lsm[B_][E_];
    int t = threadIdx.x;
#pragma unroll
    for (int b = 0; b < B_; b++) {
        float acc = Tb1[t];
#pragma unroll
        for (int c = 0; c < 32; c++) acc += g_hpart[b][c][t];
        hsm[b][t] = fmaxf(acc, 0.f);
    }
    __syncthreads();
    if (t < B_ * E_) {
        int b = t / E_, e = t % E_;
        float acc = Tb2[e];
#pragma unroll 8
        for (int j = 0; j < H_; j++) acc += hsm[b][j] * TW2[j * E_ + e];
        lsm[b][e] = acc;
    }
    __syncthreads();
    if (t < B_) {
        float mx = lsm[t][0];
#pragma unroll
        for (int e = 1; e < E_; e++) mx = fmaxf(mx, lsm[t][e]);
        float ex[E_], s = 0.f;
#pragma unroll
        for (int e = 0; e < E_; e++) { ex[e] = expf(lsm[t][e] - mx); s += ex[e]; }
        float inv = 1.f / s;
#pragma unroll
        for (int e = 0; e < E_; e++) g_task_w[t][e] = ex[e] * inv;
    }
    if (t == 0) g_alpha = 1.f / (1.f + expf(-alpha[0]));
}

// ---------------- main fused kernel ----------------
// grid 128 CTAs, 256 threads. Tile: 128 rows x 128 cols (full H), K-loop of 32,
// double-buffered SMEM, 8x8 per-thread microtile with packed f32x2 FMAs.
extern __shared__ float smem_dyn[];

__global__ __launch_bounds__(NTHREADS, 1)
void main_fused_kernel(const float* __restrict__ X,
                       const float* __restrict__ W1,
                       const float* __restrict__ b1,
                       const float* __restrict__ W2,
                       const float* __restrict__ b2,
                       float* __restrict__ out) {
    float* Xs  = smem_dyn;                    // [2][KC][XPAD], transposed (k-major)
    float* Ws  = Xs + 2 * KC * XPAD;          // [2][KC][H_]
    float* W2s = Ws + 2 * KC * H_;            // [H_][E_]
    float* b2s = W2s + H_ * E_;               // [E_]

    const int tid = threadIdx.x;
    const int tx = tid & 15, ty = tid >> 4;
    const int m0 = blockIdx.x * MT;

    // stage W2/b2 once
    for (int i = tid; i < H_ * E_; i += NTHREADS) W2s[i] = W2[i];
    if (tid < E_) b2s[tid] = b2[tid];

    unsigned long long acc[4][8];
#pragma unroll
    for (int i2 = 0; i2 < 4; i2++)
#pragma unroll
        for (int j = 0; j < 8; j++) acc[i2][j] = 0ULL;

    float4 xr[4], wr[4];

    // global->reg loaders (chunk ch)
    auto load_g = [&](int ch) {
        const int k0 = ch * KC;
#pragma unroll
        for (int l = 0; l < 4; l++) {
            int q  = tid + NTHREADS * l;
            int m  = q >> 3, kq = q & 7;
            xr[l] = *(const float4*)(X + (size_t)(m0 + m) * D_ + k0 + kq * 4);
            int kw = q >> 5, nq = q & 31;
            wr[l] = *(const float4*)(W1 + (size_t)(k0 + kw) * H_ + nq * 4);
        }
    };
    auto store_s = [&](int buf) {
        float* Xb = Xs + buf * KC * XPAD;
        float* Wb = Ws + buf * KC * H_;
#pragma unroll
        for (int l = 0; l < 4; l++) {
            int q = tid + NTHREADS * l;
            int m = q >> 3, kq = q & 7;
            Xb[(kq * 4 + 0) * XPAD + m] = xr[l].x;
            Xb[(kq * 4 + 1) * XPAD + m] = xr[l].y;
            Xb[(kq * 4 + 2) * XPAD + m] = xr[l].z;
            Xb[(kq * 4 + 3) * XPAD + m] = xr[l].w;
            int kw = q >> 5, nq = q & 31;
            *(float4*)(Wb + kw * H_ + nq * 4) = wr[l];
        }
    };

    const int NCH = D_ / KC;  // 128
    load_g(0);
    store_s(0);

    for (int ch = 0; ch < NCH; ch++) {
        int cur = ch & 1;
        __syncthreads();
        if (ch + 1 < NCH) load_g(ch + 1);

        const float* Xb = Xs + cur * KC * XPAD;
        const float* Wb = Ws + cur * KC * H_;
#pragma unroll
        for (int kk = 0; kk < KC; kk++) {
            ulonglong2 a01 = *(const ulonglong2*)(Xb + kk * XPAD + ty * 8);
            ulonglong2 a23 = *(const ulonglong2*)(Xb + kk * XPAD + ty * 8 + 4);
            float4 bv0 = *(const float4*)(Wb + kk * H_ + tx * 8);
            float4 bv1 = *(const float4*)(Wb + kk * H_ + tx * 8 + 4);
            unsigned long long aa0 = a01.x, aa1 = a01.y, aa2 = a23.x, aa3 = a23.y;
            unsigned long long bb[8];
            bb[0] = pack_dup(bv0.x); bb[1] = pack_dup(bv0.y);
            bb[2] = pack_dup(bv0.z); bb[3] = pack_dup(bv0.w);
            bb[4] = pack_dup(bv1.x); bb[5] = pack_dup(bv1.y);
            bb[6] = pack_dup(bv1.z); bb[7] = pack_dup(bv1.w);
#pragma unroll
            for (int j = 0; j < 8; j++) {
                fma2(acc[0][j], aa0, bb[j]);
                fma2(acc[1][j], aa1, bb[j]);
                fma2(acc[2][j], aa2, bb[j]);
                fma2(acc[3][j], aa3, bb[j]);
            }
        }
        if (ch + 1 < NCH) store_s(cur ^ 1);
    }

    // ---- epilogue: bias + relu ----
    float b1v[8];
#pragma unroll
    for (int j = 0; j < 8; j++) b1v[j] = __ldg(b1 + tx * 8 + j);

    float h[8][8];
#pragma unroll
    for (int i2 = 0; i2 < 4; i2++)
#pragma unroll
        for (int j = 0; j < 8; j++) {
            float2 v = unpack2(acc[i2][j]);
            h[2 * i2 + 0][j] = fmaxf(v.x + b1v[j], 0.f);
            h[2 * i2 + 1][j] = fmaxf(v.y + b1v[j], 0.f);
        }

    // ---- partial logits: pl[e][i] over this thread's 8 h-columns ----
    float pl[E_][8];
#pragma unroll
    for (int e = 0; e < E_; e++)
#pragma unroll
        for (int i = 0; i < 8; i++) pl[e][i] = 0.f;

#pragma unroll
    for (int j = 0; j < 8; j++) {
        int col = tx * 8 + j;
#pragma unroll
        for (int e = 0; e < E_; e++) {
            float w = W2s[col * E_ + e];
#pragma unroll
            for (int i = 0; i < 8; i++) pl[e][i] += h[i][j] * w;
        }
    }

    // ---- reduce over the 16 tx-lanes (half-warp butterfly) ----
#pragma unroll
    for (int off = 8; off >= 1; off >>= 1)
#pragma unroll
        for (int e = 0; e < E_; e++)
#pragma unroll
            for (int i = 0; i < 8; i++)
                pl[e][i] += __shfl_xor_sync(0xffffffffu, pl[e][i], off);

    // ---- per-row routing math (one lane per 8 rows) ----
    if (tx == 0) {
        const float a = g_alpha;
        const float oma = 1.f - a;
#pragma unroll
        for (int i = 0; i < 8; i++) {
            int row = m0 + ty * 8 + i;
            int bb  = row >> 12;  // row / S_
            float l[E_];
            float mx = -3.4e38f;
#pragma unroll
            for (int e = 0; e < E_; e++) {
                l[e] = pl[e][i] + b2s[e];
                mx = fmaxf(mx, l[e]);
            }
            float r[E_], s = 0.f;
#pragma unroll
            for (int e = 0; e < E_; e++) { r[e] = expf(l[e] - mx); s += r[e]; }
            float inv = 1.f / s;
#pragma unroll
            for (int e = 0; e < E_; e++) r[e] = oma * r[e] * inv + a * g_task_w[bb][e];

            // top-2 (strict > keeps lowest index on ties, matching jax top_k)
            int i1 = 0; float v1 = r[0];
#pragma unroll
            for (int e = 1; e < E_; e++) if (r[e] > v1) { v1 = r[e]; i1 = e; }
            int isec = (i1 == 0) ? 1 : 0; float v2 = r[isec];
#pragma unroll
            for (int e = 0; e < E_; e++)
                if (e != i1 && e != isec && r[e] > v2) { v2 = r[e]; isec = e; }

            float e2  = expf(v2 - v1);
            float den = 1.f / (1.f + e2);
            float o[E_];
#pragma unroll
            for (int e = 0; e < E_; e++) o[e] = 0.f;
            o[i1]   = den;
            o[isec] = e2 * den;

            float4* op = (float4*)(out + (size_t)row * E_);
            op[0] = make_float4(o[0], o[1], o[2], o[3]);
            op[1] = make_float4(o[4], o[5], o[6], o[7]);
        }
    }
}

// ---------------- launch ----------------
extern "C" void kernel_launch(void* const* d_in, const int* in_sizes, int n_in,
                              void* d_out, int out_size) {
    const float* X     = (const float*)d_in[0];
    const float* task  = (const float*)d_in[1];
    const float* W1    = (const float*)d_in[2];
    const float* b1    = (const float*)d_in[3];
    const float* W2    = (const float*)d_in[4];
    const float* b2    = (const float*)d_in[5];
    const float* TW1   = (const float*)d_in[6];
    const float* Tb1   = (const float*)d_in[7];
    const float* TW2   = (const float*)d_in[8];
    const float* Tb2   = (const float*)d_in[9];
    const float* alpha = (const float*)d_in[10];
    float* out = (float*)d_out;

    const int smem_bytes = (2 * KC * XPAD + 2 * KC * H_ + H_ * E_ + E_) * (int)sizeof(float);
    cudaFuncSetAttribute(main_fused_kernel,
                         cudaFuncAttributeMaxDynamicSharedMemorySize, smem_bytes);

    task_partial_kernel<<<dim3(32, B_), 128>>>(task, TW1);
    task_finish_kernel<<<1, 128>>>(Tb1, TW2, Tb2, alpha);
    main_fused_kernel<<<M_ / MT, NTHREADS, smem_bytes>>>(X, W1, b1, W2, b2, out);
}

// round 6
// speedup vs baseline: 1.5854x; 1.5854x over previous
#include <cuda_runtime.h>
#include <cuda_fp16.h>
#include <math.h>
#include <stdint.h>

#define B_ 4
#define S_ 4096
#define D_ 4096
#define H_ 128
#define E_ 8
#define M_ (B_*S_)

#define MTILE 64
#define KT 32
#define NCHUNK (D_/KT)        // 128
#define NTH 256
#define PITCH 80              // smem row pitch bytes (40 fp16)
#define APLANE (64*PITCH)     // 5120
#define BPLANE (128*PITCH)    // 10240
#define STAGE (2*APLANE + 2*BPLANE)  // 30720: Ah Al Bh Bl
#define OFF_W2 (2*STAGE)      // 61440
#define OFF_B1 (OFF_W2 + H_*E_*4)
#define OFF_B2 (OFF_B1 + H_*4)
#define SMEM_BYTES (OFF_B2 + 64)

#define LO_SCALE 2048.0f
#define LO_INV   (1.0f/2048.0f)

// ---------------- device globals ----------------
__device__ __align__(16) unsigned short g_W[2][H_ * D_]; // W1^T planes [hi, lo*2048][h*D+k]
__device__ float g_hpart[B_][128][H_];
__device__ float g_task_w[B_][E_];
__device__ float g_alpha;

// ---------------- helpers ----------------
__device__ __forceinline__ unsigned s2u(const void* p) {
    unsigned r;
    asm("{ .reg .u64 t; cvta.to.shared.u64 t, %1; cvt.u32.u64 %0, t; }" : "=r"(r) : "l"(p));
    return r;
}
__device__ __forceinline__ unsigned pkh(float lo, float hi) { // f16x2 {lo, hi}
    unsigned r;
    asm("cvt.rn.f16x2.f32 %0, %1, %2;" : "=r"(r) : "f"(hi), "f"(lo));
    return r;
}
__device__ __forceinline__ void ldmx4(unsigned* r, unsigned a) {
    asm volatile("ldmatrix.sync.aligned.m8n8.x4.shared.b16 {%0,%1,%2,%3}, [%4];"
                 : "=r"(r[0]), "=r"(r[1]), "=r"(r[2]), "=r"(r[3]) : "r"(a));
}
__device__ __forceinline__ void mma16816(float* c, const unsigned* a, const unsigned* b) {
    asm volatile(
        "mma.sync.aligned.m16n8k16.row.col.f32.f16.f16.f32 "
        "{%0,%1,%2,%3}, {%4,%5,%6,%7}, {%8,%9}, {%0,%1,%2,%3};"
        : "+f"(c[0]), "+f"(c[1]), "+f"(c[2]), "+f"(c[3])
        : "r"(a[0]), "r"(a[1]), "r"(a[2]), "r"(a[3]), "r"(b[0]), "r"(b[1]));
}

// ---------------- prelude: W1 transpose + fp16 split (lo scaled by 2048) ----------------
__global__ void split_w1_kernel(const float* __restrict__ W1) {
    __shared__ float ts[32][33];
    int k0 = blockIdx.x * 32, h0 = blockIdx.y * 32;
    int tx = threadIdx.x, ty = threadIdx.y;
    ts[ty][tx] = W1[(size_t)(k0 + ty) * H_ + h0 + tx];
    __syncthreads();
    float v = ts[tx][ty];                 // (k=k0+tx, h=h0+ty)
    __half hv = __float2half_rn(v);
    float lo = (v - __half2float(hv)) * LO_SCALE;
    __half lv = __float2half_rn(lo);
    size_t idx = (size_t)(h0 + ty) * D_ + k0 + tx;
    g_W[0][idx] = __half_as_ushort(hv);
    g_W[1][idx] = __half_as_ushort(lv);
}

// ---------------- task router ----------------
__global__ void task_partial_kernel(const float* __restrict__ task,
                                    const float* __restrict__ TW1) {
    int c = blockIdx.x, b = blockIdx.y, t = threadIdx.x;
    const float* tp = task + (size_t)b * D_ + c * 32;
    const float* w  = TW1 + (size_t)(c * 32) * H_ + t;
    float acc = 0.f;
#pragma unroll
    for (int d = 0; d < 32; d++) acc += tp[d] * w[(size_t)d * H_];
    g_hpart[b][c][t] = acc;
}

__global__ void task_finish_kernel(const float* __restrict__ Tb1,
                                   const float* __restrict__ TW2,
                                   const float* __restrict__ Tb2,
                                   const float* __restrict__ alpha) {
    __shared__ float hsm[B_][H_];
    __shared__ float lsm[B_][E_];
    int t = threadIdx.x;
#pragma unroll
    for (int b = 0; b < B_; b++) {
        float acc = Tb1[t];
        for (int c = 0; c < 128; c++) acc += g_hpart[b][c][t];
        hsm[b][t] = fmaxf(acc, 0.f);
    }
    __syncthreads();
    if (t < B_ * E_) {
        int b = t / E_, e = t % E_;
        float acc = Tb2[e];
#pragma unroll 8
        for (int j = 0; j < H_; j++) acc += hsm[b][j] * TW2[j * E_ + e];
        lsm[b][e] = acc;
    }
    __syncthreads();
    if (t < B_) {
        float mx = lsm[t][0];
#pragma unroll
        for (int e = 1; e < E_; e++) mx = fmaxf(mx, lsm[t][e]);
        float ex[E_], s = 0.f;
#pragma unroll
        for (int e = 0; e < E_; e++) { ex[e] = expf(lsm[t][e] - mx); s += ex[e]; }
        float inv = 1.f / s;
#pragma unroll
        for (int e = 0; e < E_; e++) g_task_w[t][e] = ex[e] * inv;
    }
    if (t == 0) g_alpha = 1.f / (1.f + expf(-alpha[0]));
}

// ---------------- main kernel: fp16-split HMMA GEMM + fused router ----------------
extern __shared__ char sm[];

__global__ __launch_bounds__(NTH, 1)
void gemm_router_kernel(const float* __restrict__ X,
                        const float* __restrict__ b1,
                        const float* __restrict__ W2,
                        const float* __restrict__ b2,
                        float* __restrict__ out) {
    const unsigned sbase = s2u(sm);
    const int tid  = threadIdx.x;
    const int lane = tid & 31;
    const int wid  = tid >> 5;
    const int wm = wid >> 2, wn = wid & 3;          // 2(m) x 4(n)
    const int m_warp = wm * 32, n_warp = wn * 32;
    const int m0 = blockIdx.x * MTILE;

    float* W2s = (float*)(sm + OFF_W2);
    float* b1s = (float*)(sm + OFF_B1);
    float* b2s = (float*)(sm + OFF_B2);
    for (int i = tid; i < H_ * E_; i += NTH) W2s[i] = W2[i];
    if (tid < H_) b1s[tid] = b1[tid];
    if (tid < E_) b2s[tid] = b2[tid];

    // fragment base addresses (bytes, shared space)
    unsigned aAddr[2], bAddr[2];
#pragma unroll
    for (int mt = 0; mt < 2; mt++)
        aAddr[mt] = sbase + (unsigned)((m_warp + mt * 16 + (lane & 15)) * PITCH + ((lane >> 4) << 4));
#pragma unroll
    for (int np = 0; np < 2; np++)
        bAddr[np] = sbase + 2 * APLANE +
                    (unsigned)((n_warp + np * 16 + ((lane >> 4) << 3) + (lane & 7)) * PITCH +
                               (((lane >> 3) & 1) << 4));

    float ch[2][4][4], cl[2][4][4];
#pragma unroll
    for (int mt = 0; mt < 2; mt++)
#pragma unroll
        for (int nt = 0; nt < 4; nt++)
#pragma unroll
            for (int q = 0; q < 4; q++) { ch[mt][nt][q] = 0.f; cl[mt][nt][q] = 0.f; }

    float4 xr[2];
    uint4  wr[2][2];

    auto load_g = [&](int ch_) {
        const int k0 = ch_ * KT;
#pragma unroll
        for (int l = 0; l < 2; l++) {
            int idx = tid + NTH * l;
            int row = idx >> 3, kq = idx & 7;
            xr[l] = *(const float4*)(X + (size_t)(m0 + row) * D_ + k0 + kq * 4);
        }
        {
            int row = tid >> 1, j = tid & 1;
            const size_t base = (size_t)row * D_ + k0 + j * 16;
#pragma unroll
            for (int p = 0; p < 2; p++) {
                wr[p][0] = *(const uint4*)(&g_W[p][base]);
                wr[p][1] = *(const uint4*)(&g_W[p][base + 8]);
            }
        }
    };
    auto store_s = [&](int buf) {
        char* st = sm + buf * STAGE;
#pragma unroll
        for (int l = 0; l < 2; l++) {
            int idx = tid + NTH * l;
            int row = idx >> 3, kq = idx & 7;
            float4 x = xr[l];
            __half h0 = __float2half_rn(x.x), h1 = __float2half_rn(x.y);
            __half h2 = __float2half_rn(x.z), h3 = __float2half_rn(x.w);
            float l0 = (x.x - __half2float(h0)) * LO_SCALE;
            float l1 = (x.y - __half2float(h1)) * LO_SCALE;
            float l2 = (x.z - __half2float(h2)) * LO_SCALE;
            float l3 = (x.w - __half2float(h3)) * LO_SCALE;
            unsigned hi01 = (unsigned)__half_as_ushort(h0) | ((unsigned)__half_as_ushort(h1) << 16);
            unsigned hi23 = (unsigned)__half_as_ushort(h2) | ((unsigned)__half_as_ushort(h3) << 16);
            *(uint2*)(st + row * PITCH + kq * 8) = make_uint2(hi01, hi23);
            *(uint2*)(st + APLANE + row * PITCH + kq * 8) = make_uint2(pkh(l0, l1), pkh(l2, l3));
        }
        {
            int row = tid >> 1, j = tid & 1;
            char* rh = st + 2 * APLANE + row * PITCH + j * 32;
            char* rl = st + 2 * APLANE + BPLANE + row * PITCH + j * 32;
            *(uint4*)(rh)      = wr[0][0];
            *(uint4*)(rh + 16) = wr[0][1];
            *(uint4*)(rl)      = wr[1][0];
            *(uint4*)(rl + 16) = wr[1][1];
        }
    };

    load_g(0);
    store_s(0);

    for (int ck = 0; ck < NCHUNK; ck++) {
        const int buf = ck & 1;
        __syncthreads();
        if (ck + 1 < NCHUNK) load_g(ck + 1);

        const unsigned bufoff = buf * STAGE;
#pragma unroll
        for (int ks = 0; ks < 2; ks++) {
            const unsigned off = bufoff + ks * 32;
            unsigned af[2][2][4];
#pragma unroll
            for (int mt = 0; mt < 2; mt++) {
                ldmx4(af[mt][0], aAddr[mt] + off);
                ldmx4(af[mt][1], aAddr[mt] + off + APLANE);
            }
            unsigned bf[2][2][4];
#pragma unroll
            for (int np = 0; np < 2; np++) {
                ldmx4(bf[np][0], bAddr[np] + off);
                ldmx4(bf[np][1], bAddr[np] + off + BPLANE);
            }
#pragma unroll
            for (int mt = 0; mt < 2; mt++)
#pragma unroll
                for (int nt = 0; nt < 4; nt++) {
                    const unsigned* bh = &bf[nt >> 1][0][(nt & 1) * 2];
                    const unsigned* bl = &bf[nt >> 1][1][(nt & 1) * 2];
                    mma16816(ch[mt][nt], af[mt][0], bh);  // hi*hi
                    mma16816(cl[mt][nt], af[mt][0], bl);  // hi*lo'
                    mma16816(cl[mt][nt], af[mt][1], bh);  // lo'*hi
                }
        }
        if (ck + 1 < NCHUNK) store_s(buf ^ 1);
    }

    // ---- epilogue: h = relu(C + b1) -> smem ----
    __syncthreads();
    float* Hs = (float*)sm;               // [64][132]
#pragma unroll
    for (int mt = 0; mt < 2; mt++)
#pragma unroll
        for (int nt = 0; nt < 4; nt++) {
            int r0 = m_warp + mt * 16 + (lane >> 2);
            int c0 = n_warp + nt * 8 + 2 * (lane & 3);
            float bb0 = b1s[c0], bb1 = b1s[c0 + 1];
            float v00 = ch[mt][nt][0] + cl[mt][nt][0] * LO_INV + bb0;
            float v01 = ch[mt][nt][1] + cl[mt][nt][1] * LO_INV + bb1;
            float v10 = ch[mt][nt][2] + cl[mt][nt][2] * LO_INV + bb0;
            float v11 = ch[mt][nt][3] + cl[mt][nt][3] * LO_INV + bb1;
            *(float2*)(Hs + r0 * 132 + c0)       = make_float2(fmaxf(v00, 0.f), fmaxf(v01, 0.f));
            *(float2*)(Hs + (r0 + 8) * 132 + c0) = make_float2(fmaxf(v10, 0.f), fmaxf(v11, 0.f));
        }
    __syncthreads();

    // ---- per-row routing (64 threads, one row each) ----
    if (tid < MTILE) {
        float pl[E_];
#pragma unroll
        for (int e = 0; e < E_; e++) pl[e] = 0.f;
        const float4* hv4 = (const float4*)(Hs + tid * 132);
#pragma unroll 8
        for (int j = 0; j < 32; j++) {
            float4 hv = hv4[j];
            int col = j * 4;
#pragma unroll
            for (int e = 0; e < E_; e++) {
                pl[e] += hv.x * W2s[(col + 0) * E_ + e];
                pl[e] += hv.y * W2s[(col + 1) * E_ + e];
                pl[e] += hv.z * W2s[(col + 2) * E_ + e];
                pl[e] += hv.w * W2s[(col + 3) * E_ + e];
            }
        }

        const int row = m0 + tid;
        const int bidx = row >> 12;
        const float a = g_alpha, oma = 1.f - a;
        float l[E_], mx = -3.4e38f;
#pragma unroll
        for (int e = 0; e < E_; e++) {
            l[e] = pl[e] + b2s[e];
            mx = fmaxf(mx, l[e]);
        }
        float r[E_], s = 0.f;
#pragma unroll
        for (int e = 0; e < E_; e++) { r[e] = expf(l[e] - mx); s += r[e]; }
        float inv = 1.f / s;
#pragma unroll
        for (int e = 0; e < E_; e++) r[e] = oma * r[e] * inv + a * g_task_w[bidx][e];

        int i1 = 0; float v1 = r[0];
#pragma unroll
        for (int e = 1; e < E_; e++) if (r[e] > v1) { v1 = r[e]; i1 = e; }
        int i2 = (i1 == 0) ? 1 : 0; float v2 = r[i2];
#pragma unroll
        for (int e = 0; e < E_; e++)
            if (e != i1 && e != i2 && r[e] > v2) { v2 = r[e]; i2 = e; }

        float e2  = expf(v2 - v1);
        float den = 1.f / (1.f + e2);
        float o[E_];
#pragma unroll
        for (int e = 0; e < E_; e++) o[e] = 0.f;
        o[i1] = den;
        o[i2] = e2 * den;
        float4* op = (float4*)(out + (size_t)row * E_);
        op[0] = make_float4(o[0], o[1], o[2], o[3]);
        op[1] = make_float4(o[4], o[5], o[6], o[7]);
    }
}

// ---------------- launch ----------------
extern "C" void kernel_launch(void* const* d_in, const int* in_sizes, int n_in,
                              void* d_out, int out_size) {
    const float* X     = (const float*)d_in[0];
    const float* task  = (const float*)d_in[1];
    const float* W1    = (const float*)d_in[2];
    const float* b1    = (const float*)d_in[3];
    const float* W2    = (const float*)d_in[4];
    const float* b2    = (const float*)d_in[5];
    const float* TW1   = (const float*)d_in[6];
    const float* Tb1   = (const float*)d_in[7];
    const float* TW2   = (const float*)d_in[8];
    const float* Tb2   = (const float*)d_in[9];
    const float* alpha = (const float*)d_in[10];
    float* out = (float*)d_out;

    cudaFuncSetAttribute(gemm_router_kernel,
                         cudaFuncAttributeMaxDynamicSharedMemorySize, SMEM_BYTES);

    split_w1_kernel<<<dim3(D_ / 32, H_ / 32), dim3(32, 32)>>>(W1);
    task_partial_kernel<<<dim3(128, B_), 128>>>(task, TW1);
    task_finish_kernel<<<1, 128>>>(Tb1, TW2, Tb2, alpha);
    gemm_router_kernel<<<M_ / MTILE, NTH, SMEM_BYTES>>>(X, b1, W2, b2, out);
}

// round 7
// speedup vs baseline: 1.9671x; 1.2407x over previous
#include <cuda_runtime.h>
#include <cuda_fp16.h>
#include <math.h>
#include <stdint.h>

#define B_ 4
#define S_ 4096
#define D_ 4096
#define H_ 128
#define E_ 8
#define M_ (B_*S_)

#define MTILE 64
#define KT 32
#define NCHUNK (D_/KT)        // 128
#define NTH 256
#define PITCH 80              // smem row pitch bytes (40 fp16)
#define APLANE (64*PITCH)     // 5120
#define BPLANE (128*PITCH)    // 10240
#define STAGE (2*APLANE + 2*BPLANE)  // 30720: Ah Al Bh Bl
#define OFF_W2 (2*STAGE)      // 61440
#define OFF_B1 (OFF_W2 + H_*E_*4)
#define OFF_B2 (OFF_B1 + H_*4)
#define SMEM_BYTES (OFF_B2 + 64)

#define LO_SCALE 2048.0f
#define LO_INV   (1.0f/2048.0f)

// ---------------- device globals ----------------
__device__ __align__(16) unsigned short g_W[2][H_ * D_]; // W1^T planes [hi, lo*2048][h*D+k]
__device__ float g_hpart[B_][128][H_];
__device__ float g_task_w[B_][E_];
__device__ float g_alpha;

// ---------------- helpers ----------------
__device__ __forceinline__ unsigned s2u(const void* p) {
    unsigned r;
    asm("{ .reg .u64 t; cvta.to.shared.u64 t, %1; cvt.u32.u64 %0, t; }" : "=r"(r) : "l"(p));
    return r;
}
__device__ __forceinline__ unsigned pkh(float lo, float hi) { // f16x2 {lo, hi}
    unsigned r;
    asm("cvt.rn.f16x2.f32 %0, %1, %2;" : "=r"(r) : "f"(hi), "f"(lo));
    return r;
}
__device__ __forceinline__ void ldmx4(unsigned* r, unsigned a) {
    asm volatile("ldmatrix.sync.aligned.m8n8.x4.shared.b16 {%0,%1,%2,%3}, [%4];"
                 : "=r"(r[0]), "=r"(r[1]), "=r"(r[2]), "=r"(r[3]) : "r"(a));
}
__device__ __forceinline__ void mma16816(float* c, const unsigned* a, const unsigned* b) {
    asm volatile(
        "mma.sync.aligned.m16n8k16.row.col.f32.f16.f16.f32 "
        "{%0,%1,%2,%3}, {%4,%5,%6,%7}, {%8,%9}, {%0,%1,%2,%3};"
        : "+f"(c[0]), "+f"(c[1]), "+f"(c[2]), "+f"(c[3])
        : "r"(a[0]), "r"(a[1]), "r"(a[2]), "r"(a[3]), "r"(b[0]), "r"(b[1]));
}
__device__ __forceinline__ void cp16(unsigned dst, const void* src) {
    asm volatile("cp.async.cg.shared.global [%0], [%1], 16;" :: "r"(dst), "l"(src) : "memory");
}
__device__ __forceinline__ void cp_commit() {
    asm volatile("cp.async.commit_group;" ::: "memory");
}
__device__ __forceinline__ void cp_wait0() {
    asm volatile("cp.async.wait_group 0;" ::: "memory");
}

// ---------------- prelude: W1 transpose + fp16 split (lo scaled by 2048) ----------------
__global__ void split_w1_kernel(const float* __restrict__ W1) {
    __shared__ float ts[32][33];
    int k0 = blockIdx.x * 32, h0 = blockIdx.y * 32;
    int tx = threadIdx.x, ty = threadIdx.y;
    ts[ty][tx] = W1[(size_t)(k0 + ty) * H_ + h0 + tx];
    __syncthreads();
    float v = ts[tx][ty];                 // (k=k0+tx, h=h0+ty)
    __half hv = __float2half_rn(v);
    float lo = (v - __half2float(hv)) * LO_SCALE;
    __half lv = __float2half_rn(lo);
    size_t idx = (size_t)(h0 + ty) * D_ + k0 + tx;
    g_W[0][idx] = __half_as_ushort(hv);
    g_W[1][idx] = __half_as_ushort(lv);
}

// ---------------- task router ----------------
__global__ void task_partial_kernel(const float* __restrict__ task,
                                    const float* __restrict__ TW1) {
    int c = blockIdx.x, b = blockIdx.y, t = threadIdx.x;
    const float* tp = task + (size_t)b * D_ + c * 32;
    const float* w  = TW1 + (size_t)(c * 32) * H_ + t;
    float acc = 0.f;
#pragma unroll
    for (int d = 0; d < 32; d++) acc += tp[d] * w[(size_t)d * H_];
    g_hpart[b][c][t] = acc;
}

__global__ void task_finish_kernel(const float* __restrict__ Tb1,
                                   const float* __restrict__ TW2,
                                   const float* __restrict__ Tb2,
                                   const float* __restrict__ alpha) {
    __shared__ float hsm[B_][H_];
    __shared__ float lsm[B_][E_];
    int t = threadIdx.x;
#pragma unroll
    for (int b = 0; b < B_; b++) {
        float acc = Tb1[t];
        for (int c = 0; c < 128; c++) acc += g_hpart[b][c][t];
        hsm[b][t] = fmaxf(acc, 0.f);
    }
    __syncthreads();
    if (t < B_ * E_) {
        int b = t / E_, e = t % E_;
        float acc = Tb2[e];
#pragma unroll 8
        for (int j = 0; j < H_; j++) acc += hsm[b][j] * TW2[j * E_ + e];
        lsm[b][e] = acc;
    }
    __syncthreads();
    if (t < B_) {
        float mx = lsm[t][0];
#pragma unroll
        for (int e = 1; e < E_; e++) mx = fmaxf(mx, lsm[t][e]);
        float ex[E_], s = 0.f;
#pragma unroll
        for (int e = 0; e < E_; e++) { ex[e] = expf(lsm[t][e] - mx); s += ex[e]; }
        float inv = 1.f / s;
#pragma unroll
        for (int e = 0; e < E_; e++) g_task_w[t][e] = ex[e] * inv;
    }
    if (t == 0) g_alpha = 1.f / (1.f + expf(-alpha[0]));
}

// ---------------- main kernel: fp16-split HMMA GEMM + fused router ----------------
extern __shared__ char sm[];

__global__ __launch_bounds__(NTH, 2)
void gemm_router_kernel(const float* __restrict__ X,
                        const float* __restrict__ b1,
                        const float* __restrict__ W2,
                        const float* __restrict__ b2,
                        float* __restrict__ out) {
    const unsigned sbase = s2u(sm);
    const int tid  = threadIdx.x;
    const int lane = tid & 31;
    const int wid  = tid >> 5;
    const int wm = wid >> 2, wn = wid & 3;          // 2(m) x 4(n)
    const int m_warp = wm * 32, n_warp = wn * 32;
    const int m0 = blockIdx.x * MTILE;

    float* W2s = (float*)(sm + OFF_W2);
    float* b1s = (float*)(sm + OFF_B1);
    float* b2s = (float*)(sm + OFF_B2);
    for (int i = tid; i < H_ * E_; i += NTH) W2s[i] = W2[i];
    if (tid < H_) b1s[tid] = b1[tid];
    if (tid < E_) b2s[tid] = b2[tid];

    // fragment base addresses (bytes, shared space)
    unsigned aAddr[2], bAddr[2];
#pragma unroll
    for (int mt = 0; mt < 2; mt++)
        aAddr[mt] = sbase + (unsigned)((m_warp + mt * 16 + (lane & 15)) * PITCH + ((lane >> 4) << 4));
#pragma unroll
    for (int np = 0; np < 2; np++)
        bAddr[np] = sbase + 2 * APLANE +
                    (unsigned)((n_warp + np * 16 + ((lane >> 4) << 3) + (lane & 7)) * PITCH +
                               (((lane >> 3) & 1) << 4));

    float ch[2][4][4], cl[2][4][4];
#pragma unroll
    for (int mt = 0; mt < 2; mt++)
#pragma unroll
        for (int nt = 0; nt < 4; nt++)
#pragma unroll
            for (int q = 0; q < 4; q++) { ch[mt][nt][q] = 0.f; cl[mt][nt][q] = 0.f; }

    // B staging thread map (row = tid>>1, half j = tid&1)
    const int brow = tid >> 1, bj = tid & 1;
    const unsigned bDstH = sbase + 2 * APLANE + (unsigned)(brow * PITCH + bj * 32);
    const unsigned bDstL = bDstH + BPLANE;
    const size_t bSrcBase = (size_t)brow * D_ + bj * 16;

    float4 xr[2];

    auto load_x = [&](int ck) {
        const int k0 = ck * KT;
#pragma unroll
        for (int l = 0; l < 2; l++) {
            int idx = tid + NTH * l;
            int row = idx >> 3, kq = idx & 7;
            xr[l] = *(const float4*)(X + (size_t)(m0 + row) * D_ + k0 + kq * 4);
        }
    };
    auto cp_b = [&](int ck, int buf) {
        const int k0 = ck * KT;
        const unsigned boff = buf * STAGE;
        cp16(bDstH + boff,      &g_W[0][bSrcBase + k0]);
        cp16(bDstH + boff + 16, &g_W[0][bSrcBase + k0 + 8]);
        cp16(bDstL + boff,      &g_W[1][bSrcBase + k0]);
        cp16(bDstL + boff + 16, &g_W[1][bSrcBase + k0 + 8]);
    };
    auto store_x = [&](int buf) {
        char* st = sm + buf * STAGE;
#pragma unroll
        for (int l = 0; l < 2; l++) {
            int idx = tid + NTH * l;
            int row = idx >> 3, kq = idx & 7;
            float4 x = xr[l];
            __half h0 = __float2half_rn(x.x), h1 = __float2half_rn(x.y);
            __half h2 = __float2half_rn(x.z), h3 = __float2half_rn(x.w);
            float l0 = (x.x - __half2float(h0)) * LO_SCALE;
            float l1 = (x.y - __half2float(h1)) * LO_SCALE;
            float l2 = (x.z - __half2float(h2)) * LO_SCALE;
            float l3 = (x.w - __half2float(h3)) * LO_SCALE;
            unsigned hi01 = (unsigned)__half_as_ushort(h0) | ((unsigned)__half_as_ushort(h1) << 16);
            unsigned hi23 = (unsigned)__half_as_ushort(h2) | ((unsigned)__half_as_ushort(h3) << 16);
            *(uint2*)(st + row * PITCH + kq * 8) = make_uint2(hi01, hi23);
            *(uint2*)(st + APLANE + row * PITCH + kq * 8) = make_uint2(pkh(l0, l1), pkh(l2, l3));
        }
    };

    // prologue: chunk 0 into buf 0
    load_x(0);
    cp_b(0, 0);
    cp_commit();
    store_x(0);

    for (int ck = 0; ck < NCHUNK; ck++) {
        const int buf = ck & 1;
        cp_wait0();
        __syncthreads();
        if (ck + 1 < NCHUNK) {
            load_x(ck + 1);
            cp_b(ck + 1, buf ^ 1);
            cp_commit();
        }

        const unsigned bufoff = buf * STAGE;
#pragma unroll
        for (int ks = 0; ks < 2; ks++) {
            const unsigned off = bufoff + ks * 32;
            unsigned af[2][2][4];
#pragma unroll
            for (int mt = 0; mt < 2; mt++) {
                ldmx4(af[mt][0], aAddr[mt] + off);
                ldmx4(af[mt][1], aAddr[mt] + off + APLANE);
            }
            unsigned bf[2][2][4];
#pragma unroll
            for (int np = 0; np < 2; np++) {
                ldmx4(bf[np][0], bAddr[np] + off);
                ldmx4(bf[np][1], bAddr[np] + off + BPLANE);
            }
#pragma unroll
            for (int mt = 0; mt < 2; mt++)
#pragma unroll
                for (int nt = 0; nt < 4; nt++) {
                    const unsigned* bh = &bf[nt >> 1][0][(nt & 1) * 2];
                    const unsigned* bl = &bf[nt >> 1][1][(nt & 1) * 2];
                    mma16816(ch[mt][nt], af[mt][0], bh);  // hi*hi
                    mma16816(cl[mt][nt], af[mt][0], bl);  // hi*lo'
                    mma16816(cl[mt][nt], af[mt][1], bh);  // lo'*hi
                }
        }
        if (ck + 1 < NCHUNK) store_x(buf ^ 1);
    }

    // ---- epilogue: h = relu(C + b1) -> smem ----
    __syncthreads();
    float* Hs = (float*)sm;               // [64][132]
#pragma unroll
    for (int mt = 0; mt < 2; mt++)
#pragma unroll
        for (int nt = 0; nt < 4; nt++) {
            int r0 = m_warp + mt * 16 + (lane >> 2);
            int c0 = n_warp + nt * 8 + 2 * (lane & 3);
            float bb0 = b1s[c0], bb1 = b1s[c0 + 1];
            float v00 = ch[mt][nt][0] + cl[mt][nt][0] * LO_INV + bb0;
            float v01 = ch[mt][nt][1] + cl[mt][nt][1] * LO_INV + bb1;
            float v10 = ch[mt][nt][2] + cl[mt][nt][2] * LO_INV + bb0;
            float v11 = ch[mt][nt][3] + cl[mt][nt][3] * LO_INV + bb1;
            *(float2*)(Hs + r0 * 132 + c0)       = make_float2(fmaxf(v00, 0.f), fmaxf(v01, 0.f));
            *(float2*)(Hs + (r0 + 8) * 132 + c0) = make_float2(fmaxf(v10, 0.f), fmaxf(v11, 0.f));
        }
    __syncthreads();

    // ---- per-row routing (64 threads, one row each) ----
    if (tid < MTILE) {
        float pl[E_];
#pragma unroll
        for (int e = 0; e < E_; e++) pl[e] = 0.f;
        const float4* hv4 = (const float4*)(Hs + tid * 132);
#pragma unroll 8
        for (int j = 0; j < 32; j++) {
            float4 hv = hv4[j];
            int col = j * 4;
#pragma unroll
            for (int e = 0; e < E_; e++) {
                pl[e] += hv.x * W2s[(col + 0) * E_ + e];
                pl[e] += hv.y * W2s[(col + 1) * E_ + e];
                pl[e] += hv.z * W2s[(col + 2) * E_ + e];
                pl[e] += hv.w * W2s[(col + 3) * E_ + e];
            }
        }

        const int row = m0 + tid;
        const int bidx = row >> 12;
        const float a = g_alpha, oma = 1.f - a;
        float l[E_], mx = -3.4e38f;
#pragma unroll
        for (int e = 0; e < E_; e++) {
            l[e] = pl[e] + b2s[e];
            mx = fmaxf(mx, l[e]);
        }
        float r[E_], s = 0.f;
#pragma unroll
        for (int e = 0; e < E_; e++) { r[e] = expf(l[e] - mx); s += r[e]; }
        float inv = 1.f / s;
#pragma unroll
        for (int e = 0; e < E_; e++) r[e] = oma * r[e] * inv + a * g_task_w[bidx][e];

        int i1 = 0; float v1 = r[0];
#pragma unroll
        for (int e = 1; e < E_; e++) if (r[e] > v1) { v1 = r[e]; i1 = e; }
        int i2 = (i1 == 0) ? 1 : 0; float v2 = r[i2];
#pragma unroll
        for (int e = 0; e < E_; e++)
            if (e != i1 && e != i2 && r[e] > v2) { v2 = r[e]; i2 = e; }

        float e2  = expf(v2 - v1);
        float den = 1.f / (1.f + e2);
        float o[E_];
#pragma unroll
        for (int e = 0; e < E_; e++) o[e] = 0.f;
        o[i1] = den;
        o[i2] = e2 * den;
        float4* op = (float4*)(out + (size_t)row * E_);
        op[0] = make_float4(o[0], o[1], o[2], o[3]);
        op[1] = make_float4(o[4], o[5], o[6], o[7]);
    }
}

// ---------------- launch ----------------
extern "C" void kernel_launch(void* const* d_in, const int* in_sizes, int n_in,
                              void* d_out, int out_size) {
    const float* X     = (const float*)d_in[0];
    const float* task  = (const float*)d_in[1];
    const float* W1    = (const float*)d_in[2];
    const float* b1    = (const float*)d_in[3];
    const float* W2    = (const float*)d_in[4];
    const float* b2    = (const float*)d_in[5];
    const float* TW1   = (const float*)d_in[6];
    const float* Tb1   = (const float*)d_in[7];
    const float* TW2   = (const float*)d_in[8];
    const float* Tb2   = (const float*)d_in[9];
    const float* alpha = (const float*)d_in[10];
    float* out = (float*)d_out;

    cudaFuncSetAttribute(gemm_router_kernel,
                         cudaFuncAttributeMaxDynamicSharedMemorySize, SMEM_BYTES);

    split_w1_kernel<<<dim3(D_ / 32, H_ / 32), dim3(32, 32)>>>(W1);
    task_partial_kernel<<<dim3(128, B_), 128>>>(task, TW1);
    task_finish_kernel<<<1, 128>>>(Tb1, TW2, Tb2, alpha);
    gemm_router_kernel<<<M_ / MTILE, NTH, SMEM_BYTES>>>(X, b1, W2, b2, out);
}

// round 8
// speedup vs baseline: 2.5485x; 1.2956x over previous
#include <cuda_runtime.h>
#include <cuda_fp16.h>
#include <math.h>
#include <stdint.h>

#define B_ 4
#define S_ 4096
#define D_ 4096
#define H_ 128
#define E_ 8
#define M_ (B_*S_)

#define MTILE 64
#define KT 64
#define NCHUNK (D_/KT)        // 64
#define NTH 256
// XOR-swizzled planes: 128B rows, chunk16 ^= (row & 7)
#define APL 8192              // 64 rows * 128B
#define BPL 16384             // 128 rows * 128B
#define OFF_AH 0
#define OFF_AL APL
#define OFF_BH (2*APL)
#define OFF_BL (2*APL + BPL)
#define STAGE (2*APL + 2*BPL) // 49152
#define OFF_W2 (2*STAGE)      // 98304
#define OFF_B1 (OFF_W2 + H_*E_*4)
#define OFF_B2 (OFF_B1 + H_*4)
#define SMEM_BYTES (OFF_B2 + 64)

#define LO_SCALE 2048.0f
#define LO_INV   (1.0f/2048.0f)

// ---------------- device globals ----------------
__device__ __align__(16) unsigned short g_W[2][H_ * D_]; // W1^T planes [hi, lo*2048][h*D+k]
__device__ float g_hpart[B_][128][H_];
__device__ float g_task_w[B_][E_];
__device__ float g_alpha;

// ---------------- helpers ----------------
__device__ __forceinline__ unsigned s2u(const void* p) {
    unsigned r;
    asm("{ .reg .u64 t; cvta.to.shared.u64 t, %1; cvt.u32.u64 %0, t; }" : "=r"(r) : "l"(p));
    return r;
}
__device__ __forceinline__ unsigned pkh(float lo, float hi) { // f16x2 {lo, hi}
    unsigned r;
    asm("cvt.rn.f16x2.f32 %0, %1, %2;" : "=r"(r) : "f"(hi), "f"(lo));
    return r;
}
__device__ __forceinline__ void ldmx4(unsigned* r, unsigned a) {
    asm volatile("ldmatrix.sync.aligned.m8n8.x4.shared.b16 {%0,%1,%2,%3}, [%4];"
                 : "=r"(r[0]), "=r"(r[1]), "=r"(r[2]), "=r"(r[3]) : "r"(a));
}
__device__ __forceinline__ void mma16816(float* c, const unsigned* a, const unsigned* b) {
    asm volatile(
        "mma.sync.aligned.m16n8k16.row.col.f32.f16.f16.f32 "
        "{%0,%1,%2,%3}, {%4,%5,%6,%7}, {%8,%9}, {%0,%1,%2,%3};"
        : "+f"(c[0]), "+f"(c[1]), "+f"(c[2]), "+f"(c[3])
        : "r"(a[0]), "r"(a[1]), "r"(a[2]), "r"(a[3]), "r"(b[0]), "r"(b[1]));
}
__device__ __forceinline__ void cp16(unsigned dst, const void* src) {
    asm volatile("cp.async.cg.shared.global [%0], [%1], 16;" :: "r"(dst), "l"(src) : "memory");
}
__device__ __forceinline__ void cp_commit() {
    asm volatile("cp.async.commit_group;" ::: "memory");
}
__device__ __forceinline__ void cp_wait0() {
    asm volatile("cp.async.wait_group 0;" ::: "memory");
}

// ---------------- prelude: W1 transpose + fp16 split (lo scaled by 2048) ----------------
__global__ void split_w1_kernel(const float* __restrict__ W1) {
    __shared__ float ts[32][33];
    int k0 = blockIdx.x * 32, h0 = blockIdx.y * 32;
    int tx = threadIdx.x, ty = threadIdx.y;
    ts[ty][tx] = W1[(size_t)(k0 + ty) * H_ + h0 + tx];
    __syncthreads();
    float v = ts[tx][ty];                 // (k=k0+tx, h=h0+ty)
    __half hv = __float2half_rn(v);
    float lo = (v - __half2float(hv)) * LO_SCALE;
    __half lv = __float2half_rn(lo);
    size_t idx = (size_t)(h0 + ty) * D_ + k0 + tx;
    g_W[0][idx] = __half_as_ushort(hv);
    g_W[1][idx] = __half_as_ushort(lv);
}

// ---------------- task router ----------------
__global__ void task_partial_kernel(const float* __restrict__ task,
                                    const float* __restrict__ TW1) {
    int c = blockIdx.x, b = blockIdx.y, t = threadIdx.x;
    const float* tp = task + (size_t)b * D_ + c * 32;
    const float* w  = TW1 + (size_t)(c * 32) * H_ + t;
    float acc = 0.f;
#pragma unroll
    for (int d = 0; d < 32; d++) acc += tp[d] * w[(size_t)d * H_];
    g_hpart[b][c][t] = acc;
}

__global__ void task_finish_kernel(const float* __restrict__ Tb1,
                                   const float* __restrict__ TW2,
                                   const float* __restrict__ Tb2,
                                   const float* __restrict__ alpha) {
    __shared__ float hsm[B_][H_];
    __shared__ float lsm[B_][E_];
    int t = threadIdx.x;
#pragma unroll
    for (int b = 0; b < B_; b++) {
        float acc = Tb1[t];
        for (int c = 0; c < 128; c++) acc += g_hpart[b][c][t];
        hsm[b][t] = fmaxf(acc, 0.f);
    }
    __syncthreads();
    if (t < B_ * E_) {
        int b = t / E_, e = t % E_;
        float acc = Tb2[e];
#pragma unroll 8
        for (int j = 0; j < H_; j++) acc += hsm[b][j] * TW2[j * E_ + e];
        lsm[b][e] = acc;
    }
    __syncthreads();
    if (t < B_) {
        float mx = lsm[t][0];
#pragma unroll
        for (int e = 1; e < E_; e++) mx = fmaxf(mx, lsm[t][e]);
        float ex[E_], s = 0.f;
#pragma unroll
        for (int e = 0; e < E_; e++) { ex[e] = expf(lsm[t][e] - mx); s += ex[e]; }
        float inv = 1.f / s;
#pragma unroll
        for (int e = 0; e < E_; e++) g_task_w[t][e] = ex[e] * inv;
    }
    if (t == 0) g_alpha = 1.f / (1.f + expf(-alpha[0]));
}

// ---------------- main kernel: fp16-split HMMA GEMM + fused router ----------------
extern __shared__ char sm[];

__global__ __launch_bounds__(NTH, 2)
void gemm_router_kernel(const float* __restrict__ X,
                        const float* __restrict__ b1,
                        const float* __restrict__ W2,
                        const float* __restrict__ b2,
                        float* __restrict__ out) {
    const unsigned sbase = s2u(sm);
    const int tid  = threadIdx.x;
    const int lane = tid & 31;
    const int wid  = tid >> 5;
    const int wm = wid >> 2, wn = wid & 3;          // 2(m) x 4(n)
    const int m_warp = wm * 32, n_warp = wn * 32;
    const int m0 = blockIdx.x * MTILE;

    float* W2s = (float*)(sm + OFF_W2);
    float* b1s = (float*)(sm + OFF_B1);
    float* b2s = (float*)(sm + OFF_B2);
    for (int i = tid; i < H_ * E_; i += NTH) W2s[i] = W2[i];
    if (tid < H_) b1s[tid] = b1[tid];
    if (tid < E_) b2s[tid] = b2[tid];

    // ldmatrix addressing (XOR swizzle: chunk16 ^= row&7; all our rows have row&7 == lane&7)
    const unsigned sxor = lane & 7;
    const unsigned c0A = lane >> 4;            // 0/1
    const unsigned c0B = (lane >> 3) & 1;      // 0/1
    unsigned aRow[2], bRow[2];
#pragma unroll
    for (int mt = 0; mt < 2; mt++)
        aRow[mt] = (unsigned)((m_warp + mt * 16 + (lane & 15)) * 128);
#pragma unroll
    for (int np = 0; np < 2; np++)
        bRow[np] = (unsigned)((n_warp + np * 16 + ((lane >> 4) << 3) + (lane & 7)) * 128);

    float ch[2][4][4], cl[2][4][4];
#pragma unroll
    for (int mt = 0; mt < 2; mt++)
#pragma unroll
        for (int nt = 0; nt < 4; nt++)
#pragma unroll
            for (int q = 0; q < 4; q++) { ch[mt][nt][q] = 0.f; cl[mt][nt][q] = 0.f; }

    float4 xr[2];

    // X loader: half h (32 floats of K) of chunk ck
    auto load_x = [&](int ck, int h) {
        const int k0 = ck * KT + h * 32;
#pragma unroll
        for (int l = 0; l < 2; l++) {
            int idx = tid + NTH * l;
            int row = idx >> 3, kq = idx & 7;
            xr[l] = *(const float4*)(X + (size_t)(m0 + row) * D_ + k0 + kq * 4);
        }
    };
    auto store_x = [&](int buf, int h) {
        char* st = sm + buf * STAGE;
#pragma unroll
        for (int l = 0; l < 2; l++) {
            int idx = tid + NTH * l;
            int row = idx >> 3, kq = idx & 7;
            float4 x = xr[l];
            __half h0 = __float2half_rn(x.x), h1 = __float2half_rn(x.y);
            __half h2 = __float2half_rn(x.z), h3 = __float2half_rn(x.w);
            float l0 = (x.x - __half2float(h0)) * LO_SCALE;
            float l1 = (x.y - __half2float(h1)) * LO_SCALE;
            float l2 = (x.z - __half2float(h2)) * LO_SCALE;
            float l3 = (x.w - __half2float(h3)) * LO_SCALE;
            unsigned hi01 = (unsigned)__half_as_ushort(h0) | ((unsigned)__half_as_ushort(h1) << 16);
            unsigned hi23 = (unsigned)__half_as_ushort(h2) | ((unsigned)__half_as_ushort(h3) << 16);
            unsigned cc = (unsigned)((h * 4 + (kq >> 1)) ^ (row & 7));
            unsigned off = (unsigned)(row * 128) + cc * 16 + (kq & 1) * 8;
            *(uint2*)(st + OFF_AH + off) = make_uint2(hi01, hi23);
            *(uint2*)(st + OFF_AL + off) = make_uint2(pkh(l0, l1), pkh(l2, l3));
        }
    };
    auto cp_b = [&](int ck, int buf) {
        const int k0 = ck * KT;
        const unsigned bo = sbase + buf * STAGE;
#pragma unroll
        for (int l = 0; l < 4; l++) {
            int idx = tid + NTH * l;
            int row = idx >> 3, cc = idx & 7;
            unsigned sw = (unsigned)((cc ^ (row & 7)) * 16) + (unsigned)(row * 128);
            const size_t src = (size_t)row * D_ + k0 + cc * 8;
            cp16(bo + OFF_BH + sw, &g_W[0][src]);
            cp16(bo + OFF_BL + sw, &g_W[1][src]);
        }
    };

    auto mma_step = [&](unsigned bufoff, int ks) {
        unsigned cA = ((c0A + 2 * ks) ^ sxor) * 16;
        unsigned cB = ((c0B + 2 * ks) ^ sxor) * 16;
        unsigned af[2][2][4];
#pragma unroll
        for (int mt = 0; mt < 2; mt++) {
            ldmx4(af[mt][0], sbase + bufoff + OFF_AH + aRow[mt] + cA);
            ldmx4(af[mt][1], sbase + bufoff + OFF_AL + aRow[mt] + cA);
        }
        unsigned bf[2][2][4];
#pragma unroll
        for (int np = 0; np < 2; np++) {
            ldmx4(bf[np][0], sbase + bufoff + OFF_BH + bRow[np] + cB);
            ldmx4(bf[np][1], sbase + bufoff + OFF_BL + bRow[np] + cB);
        }
#pragma unroll
        for (int mt = 0; mt < 2; mt++)
#pragma unroll
            for (int nt = 0; nt < 4; nt++) {
                const unsigned* bh = &bf[nt >> 1][0][(nt & 1) * 2];
                const unsigned* bl = &bf[nt >> 1][1][(nt & 1) * 2];
                mma16816(ch[mt][nt], af[mt][0], bh);  // hi*hi
                mma16816(cl[mt][nt], af[mt][0], bl);  // hi*lo'
                mma16816(cl[mt][nt], af[mt][1], bh);  // lo'*hi
            }
    };

    // prologue: chunk 0 into buf 0
    load_x(0, 0);
    cp_b(0, 0);
    cp_commit();
    store_x(0, 0);
    load_x(0, 1);
    store_x(0, 1);

    for (int ck = 0; ck < NCHUNK; ck++) {
        const int buf = ck & 1;
        const unsigned bufoff = buf * STAGE;
        const bool more = (ck + 1 < NCHUNK);
        cp_wait0();
        __syncthreads();
        if (more) {
            load_x(ck + 1, 0);
            cp_b(ck + 1, buf ^ 1);
            cp_commit();
        }
        mma_step(bufoff, 0);
        mma_step(bufoff, 1);
        if (more) {
            store_x(buf ^ 1, 0);
            load_x(ck + 1, 1);
        }
        mma_step(bufoff, 2);
        mma_step(bufoff, 3);
        if (more) store_x(buf ^ 1, 1);
    }

    // ---- epilogue: h = relu(C + b1) -> smem ----
    __syncthreads();
    float* Hs = (float*)sm;               // [64][132]
#pragma unroll
    for (int mt = 0; mt < 2; mt++)
#pragma unroll
        for (int nt = 0; nt < 4; nt++) {
            int r0 = m_warp + mt * 16 + (lane >> 2);
            int c0 = n_warp + nt * 8 + 2 * (lane & 3);
            float bb0 = b1s[c0], bb1 = b1s[c0 + 1];
            float v00 = ch[mt][nt][0] + cl[mt][nt][0] * LO_INV + bb0;
            float v01 = ch[mt][nt][1] + cl[mt][nt][1] * LO_INV + bb1;
            float v10 = ch[mt][nt][2] + cl[mt][nt][2] * LO_INV + bb0;
            float v11 = ch[mt][nt][3] + cl[mt][nt][3] * LO_INV + bb1;
            *(float2*)(Hs + r0 * 132 + c0)       = make_float2(fmaxf(v00, 0.f), fmaxf(v01, 0.f));
            *(float2*)(Hs + (r0 + 8) * 132 + c0) = make_float2(fmaxf(v10, 0.f), fmaxf(v11, 0.f));
        }
    __syncthreads();

    // ---- per-row routing (64 threads, one row each) ----
    if (tid < MTILE) {
        float pl[E_];
#pragma unroll
        for (int e = 0; e < E_; e++) pl[e] = 0.f;
        const float4* hv4 = (const float4*)(Hs + tid * 132);
#pragma unroll 8
        for (int j = 0; j < 32; j++) {
            float4 hv = hv4[j];
            int col = j * 4;
#pragma unroll
            for (int e = 0; e < E_; e++) {
                pl[e] += hv.x * W2s[(col + 0) * E_ + e];
                pl[e] += hv.y * W2s[(col + 1) * E_ + e];
                pl[e] += hv.z * W2s[(col + 2) * E_ + e];
                pl[e] += hv.w * W2s[(col + 3) * E_ + e];
            }
        }

        const int row = m0 + tid;
        const int bidx = row >> 12;
        const float a = g_alpha, oma = 1.f - a;
        float l[E_], mx = -3.4e38f;
#pragma unroll
        for (int e = 0; e < E_; e++) {
            l[e] = pl[e] + b2s[e];
            mx = fmaxf(mx, l[e]);
        }
        float r[E_], s = 0.f;
#pragma unroll
        for (int e = 0; e < E_; e++) { r[e] = expf(l[e] - mx); s += r[e]; }
        float inv = 1.f / s;
#pragma unroll
        for (int e = 0; e < E_; e++) r[e] = oma * r[e] * inv + a * g_task_w[bidx][e];

        int i1 = 0; float v1 = r[0];
#pragma unroll
        for (int e = 1; e < E_; e++) if (r[e] > v1) { v1 = r[e]; i1 = e; }
        int i2 = (i1 == 0) ? 1 : 0; float v2 = r[i2];
#pragma unroll
        for (int e = 0; e < E_; e++)
            if (e != i1 && e != i2 && r[e] > v2) { v2 = r[e]; i2 = e; }

        float e2  = expf(v2 - v1);
        float den = 1.f / (1.f + e2);
        float o[E_];
#pragma unroll
        for (int e = 0; e < E_; e++) o[e] = 0.f;
        o[i1] = den;
        o[i2] = e2 * den;
        float4* op = (float4*)(out + (size_t)row * E_);
        op[0] = make_float4(o[0], o[1], o[2], o[3]);
        op[1] = make_float4(o[4], o[5], o[6], o[7]);
    }
}

// ---------------- launch ----------------
extern "C" void kernel_launch(void* const* d_in, const int* in_sizes, int n_in,
                              void* d_out, int out_size) {
    const float* X     = (const float*)d_in[0];
    const float* task  = (const float*)d_in[1];
    const float* W1    = (const float*)d_in[2];
    const float* b1    = (const float*)d_in[3];
    const float* W2    = (const float*)d_in[4];
    const float* b2    = (const float*)d_in[5];
    const float* TW1   = (const float*)d_in[6];
    const float* Tb1   = (const float*)d_in[7];
    const float* TW2   = (const float*)d_in[8];
    const float* Tb2   = (const float*)d_in[9];
    const float* alpha = (const float*)d_in[10];
    float* out = (float*)d_out;

    cudaFuncSetAttribute(gemm_router_kernel,
                         cudaFuncAttributeMaxDynamicSharedMemorySize, SMEM_BYTES);

    split_w1_kernel<<<dim3(D_ / 32, H_ / 32), dim3(32, 32)>>>(W1);
    task_partial_kernel<<<dim3(128, B_), 128>>>(task, TW1);
    task_finish_kernel<<<1, 128>>>(Tb1, TW2, Tb2, alpha);
    gemm_router_kernel<<<M_ / MTILE, NTH, SMEM_BYTES>>>(X, b1, W2, b2, out);
}